// round 7
// baseline (speedup 1.0000x reference)
#include <cuda_runtime.h>

// ---------------------------------------------------------------------------
// AttentionLayer, 3xTF32 (hi=tf32(x), lo=x-hi; keep hh+lh+hl terms).
// R6: split done at smem-stage time (16 splits/thread/tile), packed
// float2{hi,lo} smem with R2's immediate-foldable addressing, pure
// LDS.64+HMMA inner loop, double-buffered smem (1 sync/tile).
// Memory footprint identical to R2 (Q,K,V,S = 1.6GB of __device__ globals).
// ---------------------------------------------------------------------------

#define HID   1024
#define SEQQ  256
#define SEQK  512
#define PAIRS 256
#define MQ    (PAIRS * SEQQ)   // 65536
#define MS    (PAIRS * SEQK)   // 131072

// Scratch (allocation-free rule: __device__ globals)
__device__ float g_Q[(size_t)MQ * HID];
__device__ float g_K[(size_t)MS * HID];
__device__ float g_V[(size_t)MS * HID];
__device__ float g_S[(size_t)PAIRS * SEQQ * SEQK];

// smem: per stage, A2 = [128 rows][20 k-slots] float2, B2 = [16 k][132 n] float2
#define A2F2 (128 * 20)
#define B2F2 (16 * 132)
#define STAGE_F2 (A2F2 + B2F2)
#define SMEM_BYTES (2 * STAGE_F2 * (int)sizeof(float2))   // 74752 B

// ---------------------------------------------------------------------------
__device__ __forceinline__ float2 split2(float x) {
    unsigned h;
    asm("cvt.rna.tf32.f32 %0, %1;" : "=r"(h) : "f"(x));
    float2 r;
    r.x = __uint_as_float(h);
    r.y = x - r.x;
    return r;
}

__device__ __forceinline__ void mma_tf32(float c[4],
                                         float a0, float a1, float a2, float a3,
                                         float b0, float b1) {
    asm("mma.sync.aligned.m16n8k8.row.col.f32.tf32.tf32.f32 "
        "{%0,%1,%2,%3}, {%4,%5,%6,%7}, {%8,%9}, {%0,%1,%2,%3};"
        : "+f"(c[0]), "+f"(c[1]), "+f"(c[2]), "+f"(c[3])
        : "r"(__float_as_uint(a0)), "r"(__float_as_uint(a1)),
          "r"(__float_as_uint(a2)), "r"(__float_as_uint(a3)),
          "r"(__float_as_uint(b0)), "r"(__float_as_uint(b1)));
}

// ---------------------------------------------------------------------------
// 3xTF32 GEMM: C[M,N] = A[M,K] * B (+bias).
//   TRANSB=false: B is [K,N] row-major.  TRANSB=true: B is [N,K] (C = A B^T).
// Block tile 128x128x16, 256 threads (2x4 warps, warp tile 64x32).
// ---------------------------------------------------------------------------
template <bool TRANSB, bool BIAS>
__global__ void __launch_bounds__(256)
gemm3x(const float* __restrict__ A, const float* __restrict__ B,
       const float* __restrict__ bias, float* __restrict__ C,
       int K, int lda, int ldb, int ldc,
       size_t sA, size_t sB, size_t sC)
{
    extern __shared__ float2 sm[];

    const int tid  = threadIdx.x;
    const int lane = tid & 31;
    const int wm   = (tid >> 5) >> 2;   // 0..1
    const int wn   = (tid >> 5) & 3;    // 0..3
    const int g    = lane >> 2;         // 0..7
    const int tg   = lane & 3;          // 0..3

    const size_t z = blockIdx.z;
    A += z * sA + (size_t)blockIdx.y * 128 * lda;
    if (TRANSB) B += z * sB + (size_t)blockIdx.x * 128 * ldb;
    else        B += z * sB + (size_t)blockIdx.x * 128;
    C += z * sC + (size_t)blockIdx.y * 128 * ldc + (size_t)blockIdx.x * 128;

    // global load coords (two float4 each for A and B)
    const int aR0 = tid >> 2, aK0 = (tid & 3) * 4;   // A: 4 consecutive k
    const int aR1 = aR0 + 64;
    int bY0, bX0, bY1;
    if (TRANSB) { bY0 = tid >> 2;  bX0 = (tid & 3) * 4;  bY1 = bY0 + 64; }  // rows=n, k contig
    else        { bY0 = tid >> 5;  bX0 = (tid & 31) * 4; bY1 = bY0 + 8;  }  // rows=k, n contig

    float4 ra0, ra1, rb0, rb1;

    auto load_tile = [&](int t) {
        const float* At = A + (size_t)t * 16;
        ra0 = *(const float4*)(At + (size_t)aR0 * lda + aK0);
        ra1 = *(const float4*)(At + (size_t)aR1 * lda + aK0);
        if (TRANSB) {
            const float* Bt = B + (size_t)t * 16;
            rb0 = *(const float4*)(Bt + (size_t)bY0 * ldb + bX0);
            rb1 = *(const float4*)(Bt + (size_t)bY1 * ldb + bX0);
        } else {
            const float* Bt = B + (size_t)t * 16 * ldb;
            rb0 = *(const float4*)(Bt + (size_t)bY0 * ldb + bX0);
            rb1 = *(const float4*)(Bt + (size_t)bY1 * ldb + bX0);
        }
    };

    // stage: split f32 -> {hi,lo} float2 at stage time, packed stores.
    auto stage = [&](int s) {
        float2* A_ = sm + s * STAGE_F2;
        float2* B_ = A_ + A2F2;
        {
            float2 s0 = split2(ra0.x), s1 = split2(ra0.y),
                   s2 = split2(ra0.z), s3 = split2(ra0.w);
            *(float4*)&A_[aR0 * 20 + aK0]     = make_float4(s0.x, s0.y, s1.x, s1.y);
            *(float4*)&A_[aR0 * 20 + aK0 + 2] = make_float4(s2.x, s2.y, s3.x, s3.y);
            s0 = split2(ra1.x); s1 = split2(ra1.y);
            s2 = split2(ra1.z); s3 = split2(ra1.w);
            *(float4*)&A_[aR1 * 20 + aK0]     = make_float4(s0.x, s0.y, s1.x, s1.y);
            *(float4*)&A_[aR1 * 20 + aK0 + 2] = make_float4(s2.x, s2.y, s3.x, s3.y);
        }
        if (TRANSB) {
            const float* v = (const float*)&rb0;
            #pragma unroll
            for (int j = 0; j < 4; ++j)
                B_[(bX0 + j) * 132 + bY0] = split2(v[j]);
            v = (const float*)&rb1;
            #pragma unroll
            for (int j = 0; j < 4; ++j)
                B_[(bX0 + j) * 132 + bY1] = split2(v[j]);
        } else {
            float2 s0 = split2(rb0.x), s1 = split2(rb0.y),
                   s2 = split2(rb0.z), s3 = split2(rb0.w);
            *(float4*)&B_[bY0 * 132 + bX0]     = make_float4(s0.x, s0.y, s1.x, s1.y);
            *(float4*)&B_[bY0 * 132 + bX0 + 2] = make_float4(s2.x, s2.y, s3.x, s3.y);
            s0 = split2(rb1.x); s1 = split2(rb1.y);
            s2 = split2(rb1.z); s3 = split2(rb1.w);
            *(float4*)&B_[bY1 * 132 + bX0]     = make_float4(s0.x, s0.y, s1.x, s1.y);
            *(float4*)&B_[bY1 * 132 + bX0 + 2] = make_float4(s2.x, s2.y, s3.x, s3.y);
        }
    };

    float acc[4][4][4];
    #pragma unroll
    for (int mi = 0; mi < 4; ++mi)
        #pragma unroll
        for (int ni = 0; ni < 4; ++ni)
            #pragma unroll
            for (int i = 0; i < 4; ++i) acc[mi][ni][i] = 0.f;

    const int nT = K >> 4;
    load_tile(0);
    stage(0);
    __syncthreads();

    for (int t = 0; t < nT; ++t) {
        if (t + 1 < nT) load_tile(t + 1);   // LDGs in flight over compute

        const float2* A_ = sm + (t & 1) * STAGE_F2;
        const float2* B_ = A_ + A2F2;

        #pragma unroll
        for (int kk = 0; kk < 2; ++kk) {
            const int k1 = kk * 8 + tg;     // runtime tg + immediate

            // B fragments: one LDS.64 each ({hi,lo} pair), pure loads
            float2 bf[4][2];
            #pragma unroll
            for (int ni = 0; ni < 4; ++ni) {
                const int n = wn * 32 + ni * 8 + g;
                bf[ni][0] = B_[k1 * 132 + n];
                bf[ni][1] = B_[(k1 + 4) * 132 + n];
            }

            #pragma unroll
            for (int mi = 0; mi < 4; ++mi) {
                const int r = wm * 64 + mi * 16 + g;
                const float2 a0 = A_[r * 20 + k1];
                const float2 a1 = A_[(r + 8) * 20 + k1];
                const float2 a2 = A_[r * 20 + k1 + 4];
                const float2 a3 = A_[(r + 8) * 20 + k1 + 4];
                #pragma unroll
                for (int ni = 0; ni < 4; ++ni) {
                    mma_tf32(acc[mi][ni], a0.x, a1.x, a2.x, a3.x, bf[ni][0].x, bf[ni][1].x); // hi*hi
                    mma_tf32(acc[mi][ni], a0.y, a1.y, a2.y, a3.y, bf[ni][0].x, bf[ni][1].x); // lo*hi
                    mma_tf32(acc[mi][ni], a0.x, a1.x, a2.x, a3.x, bf[ni][0].y, bf[ni][1].y); // hi*lo
                }
            }
        }

        if (t + 1 < nT) {
            stage((t + 1) & 1);   // writes other buffer; prior sync protects it
            __syncthreads();      // single barrier per tile
        }
    }

    // epilogue
    const float* bptr = BIAS ? (bias + (size_t)blockIdx.x * 128) : bias;
    #pragma unroll
    for (int mi = 0; mi < 4; ++mi) {
        const int r = wm * 64 + mi * 16 + g;
        #pragma unroll
        for (int ni = 0; ni < 4; ++ni) {
            const int cn = wn * 32 + ni * 8 + tg * 2;
            float b0 = 0.f, b1 = 0.f;
            if (BIAS) { b0 = bptr[cn]; b1 = bptr[cn + 1]; }
            float2 v0 = make_float2(acc[mi][ni][0] + b0, acc[mi][ni][1] + b1);
            float2 v1 = make_float2(acc[mi][ni][2] + b0, acc[mi][ni][3] + b1);
            *(float2*)(C + (size_t)r * ldc + cn)       = v0;
            *(float2*)(C + (size_t)(r + 8) * ldc + cn) = v1;
        }
    }
}

// ---------------------------------------------------------------------------
// Softmax over rows of S [pairs,256,512] in place + column-sum into scores.
// ---------------------------------------------------------------------------
__global__ void __launch_bounds__(256)
softmax_scores(float* __restrict__ S, float* __restrict__ scores)
{
    const int pair = blockIdx.y;
    const int w    = threadIdx.x >> 5;
    const int lane = threadIdx.x & 31;

    __shared__ float colsum[SEQK];
    for (int i = threadIdx.x; i < SEQK; i += 256) colsum[i] = 0.f;
    __syncthreads();

    float* row = S + (size_t)pair * SEQQ * SEQK + (size_t)(blockIdx.x * 8 + w) * SEQK;

    float v[16];
    #pragma unroll
    for (int i = 0; i < 16; ++i) v[i] = row[lane + 32 * i];

    float m = v[0];
    #pragma unroll
    for (int i = 1; i < 16; ++i) m = fmaxf(m, v[i]);
    #pragma unroll
    for (int o = 16; o; o >>= 1) m = fmaxf(m, __shfl_xor_sync(0xffffffffu, m, o));

    float s = 0.f;
    #pragma unroll
    for (int i = 0; i < 16; ++i) { v[i] = __expf(v[i] - m); s += v[i]; }
    #pragma unroll
    for (int o = 16; o; o >>= 1) s += __shfl_xor_sync(0xffffffffu, s, o);

    const float inv = 1.f / s;
    #pragma unroll
    for (int i = 0; i < 16; ++i) {
        const float p = v[i] * inv;
        row[lane + 32 * i] = p;
        atomicAdd(&colsum[lane + 32 * i], p);
    }
    __syncthreads();
    for (int i = threadIdx.x; i < SEQK; i += 256)
        atomicAdd(&scores[(size_t)pair * SEQK + i], colsum[i]);
}

// ---------------------------------------------------------------------------
// kernel_launch
// inputs: query, source, Wq, bq, Wk, bk, Wv, bv
// output: context [8,32,256,1024] then attention_scores [8,32,512]
// ---------------------------------------------------------------------------
extern "C" void kernel_launch(void* const* d_in, const int* in_sizes, int n_in,
                              void* d_out, int out_size)
{
    const float* query  = (const float*)d_in[0];
    const float* source = (const float*)d_in[1];
    const float* Wq = (const float*)d_in[2];
    const float* bq = (const float*)d_in[3];
    const float* Wk = (const float*)d_in[4];
    const float* bk = (const float*)d_in[5];
    const float* Wv = (const float*)d_in[6];
    const float* bv = (const float*)d_in[7];

    float* ctx    = (float*)d_out;
    float* scores = ctx + (size_t)PAIRS * SEQQ * HID;

    float *Q, *Kb, *Vb, *S;
    cudaGetSymbolAddress((void**)&Q,  g_Q);
    cudaGetSymbolAddress((void**)&Kb, g_K);
    cudaGetSymbolAddress((void**)&Vb, g_V);
    cudaGetSymbolAddress((void**)&S,  g_S);

    // opt-in to >48KB dynamic smem (host-side attribute, capture-safe)
    cudaFuncSetAttribute(gemm3x<false, true>,  cudaFuncAttributeMaxDynamicSharedMemorySize, SMEM_BYTES);
    cudaFuncSetAttribute(gemm3x<true,  false>, cudaFuncAttributeMaxDynamicSharedMemorySize, SMEM_BYTES);
    cudaFuncSetAttribute(gemm3x<false, false>, cudaFuncAttributeMaxDynamicSharedMemorySize, SMEM_BYTES);

    cudaMemsetAsync(scores, 0, (size_t)PAIRS * SEQK * sizeof(float));

    dim3 blk(256);
    // projections (N = K = 1024)
    gemm3x<false, true><<<dim3(HID / 128, MQ / 128, 1), blk, SMEM_BYTES>>>(
        query, Wq, bq, Q, HID, HID, HID, HID, 0, 0, 0);
    gemm3x<false, true><<<dim3(HID / 128, MS / 128, 1), blk, SMEM_BYTES>>>(
        source, Wk, bk, Kb, HID, HID, HID, HID, 0, 0, 0);
    gemm3x<false, true><<<dim3(HID / 128, MS / 128, 1), blk, SMEM_BYTES>>>(
        source, Wv, bv, Vb, HID, HID, HID, HID, 0, 0, 0);
    // logits S = Q K^T (batched over pairs)
    gemm3x<true, false><<<dim3(SEQK / 128, SEQQ / 128, PAIRS), blk, SMEM_BYTES>>>(
        Q, Kb, nullptr, S, HID, HID, HID, SEQK,
        (size_t)SEQQ * HID, (size_t)SEQK * HID, (size_t)SEQQ * SEQK);
    // softmax + scores
    softmax_scores<<<dim3(SEQQ / 8, PAIRS), 256>>>(S, scores);
    // context = P V (batched)
    gemm3x<false, false><<<dim3(HID / 128, SEQQ / 128, PAIRS), blk, SMEM_BYTES>>>(
        S, Vb, nullptr, ctx, SEQK, SEQK, HID, HID,
        (size_t)SEQQ * SEQK, (size_t)SEQK * HID, (size_t)SEQQ * HID);
}

// round 8
// speedup vs baseline: 1.8388x; 1.8388x over previous
#include <cuda_runtime.h>

// ---------------------------------------------------------------------------
// AttentionLayer, 3xTF32 (hi=tf32(x), lo=x-hi; hh+lh+hl terms).
// R7 = R2 core (raw-float smem, immediate-foldable LDS, inner-loop splits,
// identical accumulation order) + cp.async staging + double buffering
// (1 sync/tile) + 2 CTAs/SM.
// ---------------------------------------------------------------------------

#define HID   1024
#define SEQQ  256
#define SEQK  512
#define PAIRS 256
#define MQ    (PAIRS * SEQQ)   // 65536
#define MS    (PAIRS * SEQK)   // 131072

// Scratch (allocation-free rule: __device__ globals)
__device__ float g_Q[(size_t)MQ * HID];
__device__ float g_K[(size_t)MS * HID];
__device__ float g_V[(size_t)MS * HID];
__device__ float g_S[(size_t)PAIRS * SEQQ * SEQK];

// ---------------------------------------------------------------------------
__device__ __forceinline__ void split_tf32(float x, unsigned &hi, unsigned &lo) {
    unsigned h;
    asm("cvt.rna.tf32.f32 %0, %1;" : "=r"(h) : "f"(x));
    hi = h;
    lo = __float_as_uint(x - __uint_as_float(h));
}

__device__ __forceinline__ void mma_tf32(float c[4], const unsigned a[4], const unsigned b[2]) {
    asm("mma.sync.aligned.m16n8k8.row.col.f32.tf32.tf32.f32 "
        "{%0,%1,%2,%3}, {%4,%5,%6,%7}, {%8,%9}, {%0,%1,%2,%3};"
        : "+f"(c[0]), "+f"(c[1]), "+f"(c[2]), "+f"(c[3])
        : "r"(a[0]), "r"(a[1]), "r"(a[2]), "r"(a[3]), "r"(b[0]), "r"(b[1]));
}

__device__ __forceinline__ void cp16(unsigned smem, const void* g) {
    asm volatile("cp.async.cg.shared.global [%0], [%1], 16;" :: "r"(smem), "l"(g));
}

// ---------------------------------------------------------------------------
// 3xTF32 GEMM: C[M,N] = A[M,K] * B (+bias).
//   TRANSB=false: B is [K,N] row-major.  TRANSB=true: B is [N,K] (C = A B^T).
// Block tile 128x128x16, 256 threads (2x4 warps, warp tile 64x32), 2 CTA/SM.
// smem (double buffered):
//   As [2][128][20] floats (k-major rows, pad 20)
//   B: TRANSB -> Bn [2][128][20] (same as A);  else Bs [2][16][136].
// ---------------------------------------------------------------------------
template <bool TRANSB, bool BIAS>
__global__ void __launch_bounds__(256, 2)
gemm3x(const float* __restrict__ A, const float* __restrict__ B,
       const float* __restrict__ bias, float* __restrict__ C,
       int K, int lda, int ldb, int ldc,
       size_t sA, size_t sB, size_t sC)
{
    constexpr int BSTRIDE = TRANSB ? 20 : 136;
    constexpr int BROWS   = TRANSB ? 128 : 16;
    __shared__ float As[2][128 * 20];
    __shared__ float Bs[2][BROWS * BSTRIDE];

    const int tid  = threadIdx.x;
    const int lane = tid & 31;
    const int wm   = (tid >> 5) >> 2;   // 0..1
    const int wn   = (tid >> 5) & 3;    // 0..3
    const int g    = lane >> 2;         // 0..7
    const int tg   = lane & 3;          // 0..3

    const size_t z = blockIdx.z;
    A += z * sA + (size_t)blockIdx.y * 128 * lda;
    if (TRANSB) B += z * sB + (size_t)blockIdx.x * 128 * ldb;
    else        B += z * sB + (size_t)blockIdx.x * 128;
    C += z * sC + (size_t)blockIdx.y * 128 * ldc + (size_t)blockIdx.x * 128;

    // staging coordinates (two 16B cp.async per operand per thread)
    const int aR0 = tid >> 2, aK0 = (tid & 3) * 4;   // k-contiguous
    const int aR1 = aR0 + 64;
    int bY0, bX0, bY1;
    if (TRANSB) { bY0 = tid >> 2;  bX0 = (tid & 3) * 4;  bY1 = bY0 + 64; }  // rows=n, k contig
    else        { bY0 = tid >> 5;  bX0 = (tid & 31) * 4; bY1 = bY0 + 8;  }  // rows=k, n contig

    const unsigned aBase = (unsigned)__cvta_generic_to_shared(&As[0][0]);
    const unsigned bBase = (unsigned)__cvta_generic_to_shared(&Bs[0][0]);
    const unsigned aDst0 = aBase + (aR0 * 20 + aK0) * 4;
    const unsigned aDst1 = aBase + (aR1 * 20 + aK0) * 4;
    const unsigned bDst0 = bBase + (bY0 * BSTRIDE + bX0) * 4;
    const unsigned bDst1 = bBase + (bY1 * BSTRIDE + bX0) * 4;
    constexpr unsigned A_STG = 128 * 20 * 4;
    constexpr unsigned B_STG = BROWS * BSTRIDE * 4;

    auto issue = [&](int t, int s) {
        const float* At = A + (size_t)t * 16;
        cp16(aDst0 + s * A_STG, At + (size_t)aR0 * lda + aK0);
        cp16(aDst1 + s * A_STG, At + (size_t)aR1 * lda + aK0);
        if (TRANSB) {
            const float* Bt = B + (size_t)t * 16;
            cp16(bDst0 + s * B_STG, Bt + (size_t)bY0 * ldb + bX0);
            cp16(bDst1 + s * B_STG, Bt + (size_t)bY1 * ldb + bX0);
        } else {
            const float* Bt = B + (size_t)t * 16 * ldb;
            cp16(bDst0 + s * B_STG, Bt + (size_t)bY0 * ldb + bX0);
            cp16(bDst1 + s * B_STG, Bt + (size_t)bY1 * ldb + bX0);
        }
        asm volatile("cp.async.commit_group;" ::: "memory");
    };

    float acc[4][4][4];
    #pragma unroll
    for (int mi = 0; mi < 4; ++mi)
        #pragma unroll
        for (int ni = 0; ni < 4; ++ni)
            #pragma unroll
            for (int i = 0; i < 4; ++i) acc[mi][ni][i] = 0.f;

    const int nT = K >> 4;
    issue(0, 0);
    asm volatile("cp.async.wait_group 0;" ::: "memory");
    __syncthreads();

    for (int t = 0; t < nT; ++t) {
        if (t + 1 < nT) issue(t + 1, (t + 1) & 1);   // async loads over compute

        const float* A_ = As[t & 1];
        const float* B_ = Bs[t & 1];

        #pragma unroll
        for (int kk = 0; kk < 2; ++kk) {
            const int k1 = kk * 8 + tg;

            // B fragments + splits (hoisted, 8 splits)
            unsigned bhi[4][2], blo[4][2];
            #pragma unroll
            for (int ni = 0; ni < 4; ++ni) {
                const int n = wn * 32 + ni * 8 + g;
                float b0, b1;
                if (TRANSB) { b0 = B_[n * 20 + k1];  b1 = B_[n * 20 + k1 + 4]; }
                else        { b0 = B_[k1 * 136 + n]; b1 = B_[(k1 + 4) * 136 + n]; }
                split_tf32(b0, bhi[ni][0], blo[ni][0]);
                split_tf32(b1, bhi[ni][1], blo[ni][1]);
            }

            #pragma unroll
            for (int mi = 0; mi < 4; ++mi) {
                const int r = wm * 64 + mi * 16 + g;
                unsigned ahi[4], alo[4];
                split_tf32(A_[r * 20 + k1],           ahi[0], alo[0]);
                split_tf32(A_[(r + 8) * 20 + k1],     ahi[1], alo[1]);
                split_tf32(A_[r * 20 + k1 + 4],       ahi[2], alo[2]);
                split_tf32(A_[(r + 8) * 20 + k1 + 4], ahi[3], alo[3]);
                #pragma unroll
                for (int ni = 0; ni < 4; ++ni) {
                    mma_tf32(acc[mi][ni], ahi, bhi[ni]);  // hi*hi
                    mma_tf32(acc[mi][ni], alo, bhi[ni]);  // lo*hi
                    mma_tf32(acc[mi][ni], ahi, blo[ni]);  // hi*lo
                }
            }
        }

        if (t + 1 < nT) {
            asm volatile("cp.async.wait_group 0;" ::: "memory");
            __syncthreads();   // single barrier per tile
        }
    }

    // epilogue
    const float* bptr = BIAS ? (bias + (size_t)blockIdx.x * 128) : bias;
    #pragma unroll
    for (int mi = 0; mi < 4; ++mi) {
        const int r = wm * 64 + mi * 16 + g;
        #pragma unroll
        for (int ni = 0; ni < 4; ++ni) {
            const int cn = wn * 32 + ni * 8 + tg * 2;
            float b0 = 0.f, b1 = 0.f;
            if (BIAS) { b0 = bptr[cn]; b1 = bptr[cn + 1]; }
            float2 v0 = make_float2(acc[mi][ni][0] + b0, acc[mi][ni][1] + b1);
            float2 v1 = make_float2(acc[mi][ni][2] + b0, acc[mi][ni][3] + b1);
            *(float2*)(C + (size_t)r * ldc + cn)       = v0;
            *(float2*)(C + (size_t)(r + 8) * ldc + cn) = v1;
        }
    }
}

// ---------------------------------------------------------------------------
// Softmax over rows of S [pairs,256,512] in place + column-sum into scores.
// ---------------------------------------------------------------------------
__global__ void __launch_bounds__(256)
softmax_scores(float* __restrict__ S, float* __restrict__ scores)
{
    const int pair = blockIdx.y;
    const int w    = threadIdx.x >> 5;
    const int lane = threadIdx.x & 31;

    __shared__ float colsum[SEQK];
    for (int i = threadIdx.x; i < SEQK; i += 256) colsum[i] = 0.f;
    __syncthreads();

    float* row = S + (size_t)pair * SEQQ * SEQK + (size_t)(blockIdx.x * 8 + w) * SEQK;

    float v[16];
    #pragma unroll
    for (int i = 0; i < 16; ++i) v[i] = row[lane + 32 * i];

    float m = v[0];
    #pragma unroll
    for (int i = 1; i < 16; ++i) m = fmaxf(m, v[i]);
    #pragma unroll
    for (int o = 16; o; o >>= 1) m = fmaxf(m, __shfl_xor_sync(0xffffffffu, m, o));

    float s = 0.f;
    #pragma unroll
    for (int i = 0; i < 16; ++i) { v[i] = __expf(v[i] - m); s += v[i]; }
    #pragma unroll
    for (int o = 16; o; o >>= 1) s += __shfl_xor_sync(0xffffffffu, s, o);

    const float inv = 1.f / s;
    #pragma unroll
    for (int i = 0; i < 16; ++i) {
        const float p = v[i] * inv;
        row[lane + 32 * i] = p;
        atomicAdd(&colsum[lane + 32 * i], p);
    }
    __syncthreads();
    for (int i = threadIdx.x; i < SEQK; i += 256)
        atomicAdd(&scores[(size_t)pair * SEQK + i], colsum[i]);
}

// ---------------------------------------------------------------------------
// kernel_launch
// inputs: query, source, Wq, bq, Wk, bk, Wv, bv
// output: context [8,32,256,1024] then attention_scores [8,32,512]
// ---------------------------------------------------------------------------
extern "C" void kernel_launch(void* const* d_in, const int* in_sizes, int n_in,
                              void* d_out, int out_size)
{
    const float* query  = (const float*)d_in[0];
    const float* source = (const float*)d_in[1];
    const float* Wq = (const float*)d_in[2];
    const float* bq = (const float*)d_in[3];
    const float* Wk = (const float*)d_in[4];
    const float* bk = (const float*)d_in[5];
    const float* Wv = (const float*)d_in[6];
    const float* bv = (const float*)d_in[7];

    float* ctx    = (float*)d_out;
    float* scores = ctx + (size_t)PAIRS * SEQQ * HID;

    float *Q, *Kb, *Vb, *S;
    cudaGetSymbolAddress((void**)&Q,  g_Q);
    cudaGetSymbolAddress((void**)&Kb, g_K);
    cudaGetSymbolAddress((void**)&Vb, g_V);
    cudaGetSymbolAddress((void**)&S,  g_S);

    cudaMemsetAsync(scores, 0, (size_t)PAIRS * SEQK * sizeof(float));

    dim3 blk(256);
    // projections (N = K = 1024)
    gemm3x<false, true><<<dim3(HID / 128, MQ / 128, 1), blk>>>(
        query, Wq, bq, Q, HID, HID, HID, HID, 0, 0, 0);
    gemm3x<false, true><<<dim3(HID / 128, MS / 128, 1), blk>>>(
        source, Wk, bk, Kb, HID, HID, HID, HID, 0, 0, 0);
    gemm3x<false, true><<<dim3(HID / 128, MS / 128, 1), blk>>>(
        source, Wv, bv, Vb, HID, HID, HID, HID, 0, 0, 0);
    // logits S = Q K^T (batched over pairs)
    gemm3x<true, false><<<dim3(SEQK / 128, SEQQ / 128, PAIRS), blk>>>(
        Q, Kb, nullptr, S, HID, HID, HID, SEQK,
        (size_t)SEQQ * HID, (size_t)SEQK * HID, (size_t)SEQQ * SEQK);
    // softmax + scores
    softmax_scores<<<dim3(SEQQ / 8, PAIRS), 256>>>(S, scores);
    // context = P V (batched)
    gemm3x<false, false><<<dim3(HID / 128, SEQQ / 128, PAIRS), blk>>>(
        S, Vb, nullptr, ctx, SEQK, SEQK, HID, HID,
        (size_t)SEQQ * SEQK, (size_t)SEQK * HID, (size_t)SEQQ * HID);
}